// round 15
// baseline (speedup 1.0000x reference)
#include <cuda_runtime.h>
#include <cstdint>

// SpatialKNNEdge fused kernel, round 14.
// grid(16, B), 512 threads. Block (bx,b) owns rows i ≡ bx (mod 16) of batch b.
//   Phase 1: stage pos SoA into SMEM + stream zeros for all 128 owned rows (1MB).
//   Phase 2: kNN — 8 threads per row (adjacent lanes), strided candidate chunks,
//            per-lane exact top-16 via unconditional carry insertion,
//            exact lex-(d,j) merge across the 8 lanes via shfl_xor + bitonic cleanup.
//   Phase 3: scatter ones (same block owns the row → block-scope fence orders after zeros).

#define NN     2048
#define FF     128
#define KK     16
#define BPB    16      // blocks per batch (row residue classes)
#define THREADS 512
#define SPLIT  8       // threads per row
#define KROWS  64      // row slots per block (covers i < 1024)

__device__ __forceinline__ bool lexlt(float da, int ja, float db, int jb) {
    return (da < db) || (da == db && ja < jb);
}

__global__ __launch_bounds__(THREADS, 2)
void knn_adj_kernel(const float* __restrict__ nodes,
                    const int*   __restrict__ T,
                    const int*   __restrict__ taus,
                    float*       __restrict__ out)
{
    const int bx  = blockIdx.x;    // row residue class 0..15
    const int b   = blockIdx.y;    // batch
    const int tid = threadIdx.x;

    __shared__ float sx[NN], sy[NN], sz[NN];

    const int Tb = T[b];
    const int tb = taus[b];
    int maxJ = Tb + tb;
    if (maxJ > NN) maxJ = NN;

    const bool block_knn = (bx < tb);
    const float INF_F = 1e30f;

    // ---- Zero phase: stream zeros for the 128 owned rows (fire-and-forget) ----
    {
        const float4 z = make_float4(0.0f, 0.0f, 0.0f, 0.0f);
        float4* obase = reinterpret_cast<float4*>(out + (size_t)b * NN * NN);
        #pragma unroll 4
        for (int idx = tid; idx < 128 * (NN / 4); idx += THREADS) {
            const int r = idx >> 9;          // local row 0..127
            const int c = idx & 511;         // float4 column
            __stcs(obase + (size_t)(bx + BPB * r) * (NN / 4) + c, z);
        }
    }

    // ---- Stage candidate positions as SoA ----
    if (block_knn) {
        for (int j = tid; j < maxJ; j += THREADS) {
            const float* p = nodes + ((size_t)(b * NN + j)) * FF;
            sx[j] = __ldg(p + 0);
            sy[j] = __ldg(p + 1);
            sz[j] = __ldg(p + 2);
        }
    }

    __syncthreads();   // spos ready for all warps

    // ---- kNN phase ----
    float ad[KK];
    int   aj[KK];
    bool  emit  = false;
    int   i_row = 0;

    // Whole-warp skip: warp w covers row slots k = 4w..4w+3, min i = bx + 64w.
    if (block_knn && (bx + 2 * (tid & ~31)) < tb) {   // 64*(tid>>5) == 2*(tid & ~31)
        const int k = tid >> 3;        // row slot 0..63
        const int h = tid & 7;         // chunk lane within row
        const int i = bx + BPB * k;    // global sink row
        const bool act = (i < tb);

        const int sg = Tb + i;         // sink node index (< maxJ when act)
        const float spx = sx[sg];
        const float spy = sy[sg];
        const float spz = sz[sg];

        #pragma unroll
        for (int s = 0; s < KK; ++s) { ad[s] = INF_F; aj[s] = 0; }

        // Strided chunks: lane h scans j = h, h+8, h+16, ... (< maxJ).
        // Per warp-iteration the 8 lanes of a row read 8 consecutive j → LDS broadcast,
        // conflict-free. Within-lane j ascending → strict-< insertion is lex-stable.
        for (int j = h; j < maxJ; j += SPLIT) {
            const float dx = spx - sx[j];
            const float dy = spy - sy[j];
            const float dz = spz - sz[j];
            float cd = __fmaf_rn(dx, dx, __fmaf_rn(dy, dy, dz * dz));
            int   cj = j;
            // Unconditional carry insertion (stable: swap only on strict <).
            #pragma unroll
            for (int s = 0; s < KK; ++s) {
                const bool lt = cd < ad[s];
                const float td = lt ? ad[s] : cd;
                const int   tj = lt ? aj[s] : cj;
                ad[s] = lt ? cd : ad[s];
                aj[s] = lt ? cj : aj[s];
                cd = td; cj = tj;
            }
        }

        // Merge the 8 sorted lists across lanes h^1, h^2, h^4 (same row k:
        // xor of low-3 bits never changes tid>>3). Both partners compute the
        // identical merged list, so subsequent rounds merge group lists.
        #pragma unroll
        for (int m = 1; m <= 4; m <<= 1) {
            // L[s] = lexmin(a[s], partner[15-s]) — bitonic result, then cleanup.
            #pragma unroll
            for (int s = 0; s < KK / 2; ++s) {
                const int t = KK - 1 - s;
                const float pdT = __shfl_xor_sync(0xFFFFFFFFu, ad[t], m);
                const int   pjT = __shfl_xor_sync(0xFFFFFFFFu, aj[t], m);
                const float pdS = __shfl_xor_sync(0xFFFFFFFFu, ad[s], m);
                const int   pjS = __shfl_xor_sync(0xFFFFFFFFu, aj[s], m);
                const bool ls = lexlt(ad[s], aj[s], pdT, pjT);
                const float nds = ls ? ad[s] : pdT;
                const int   njs = ls ? aj[s] : pjT;
                const bool lt2 = lexlt(ad[t], aj[t], pdS, pjS);
                const float ndt = lt2 ? ad[t] : pdS;
                const int   njt = lt2 ? aj[t] : pjS;
                ad[s] = nds; aj[s] = njs;
                ad[t] = ndt; aj[t] = njt;
            }
            // Bitonic cleanup: sort the bitonic 16-sequence ascending.
            #pragma unroll
            for (int st = KK / 2; st >= 1; st >>= 1) {
                #pragma unroll
                for (int s = 0; s < KK; ++s) {
                    if ((s & st) == 0) {
                        const int v = s + st;
                        const bool sw = lexlt(ad[v], aj[v], ad[s], aj[s]);
                        const float td = sw ? ad[v] : ad[s];
                        const int   tj = sw ? aj[v] : aj[s];
                        const float ud = sw ? ad[s] : ad[v];
                        const int   uj = sw ? aj[s] : aj[v];
                        ad[s] = td; aj[s] = tj;
                        ad[v] = ud; aj[v] = uj;
                    }
                }
            }
        }

        if (act && h == 0) { emit = true; i_row = i; }
    }

    __syncthreads();   // block-scope fence: zeros ordered before ones (same block owns row)

    // ---- Scatter ones: real (d < INF) and causal (nbr < i) ----
    if (emit) {
        const size_t base = ((size_t)(b * NN + i_row)) * NN;
        #pragma unroll
        for (int s = 0; s < KK; ++s) {
            if (ad[s] < INF_F && aj[s] < i_row) {
                out[base + aj[s]] = 1.0f;
            }
        }
    }
}

extern "C" void kernel_launch(void* const* d_in, const int* in_sizes, int n_in,
                              void* d_out, int out_size) {
    const float* nodes = (const float*)d_in[0];
    const int*   T     = (const int*)  d_in[1];
    const int*   taus  = (const int*)  d_in[2];
    float*       out   = (float*)      d_out;

    const int B = in_sizes[1];   // length of T

    dim3 grid(BPB, B);
    knn_adj_kernel<<<grid, THREADS>>>(nodes, T, taus, out);
}

// round 16
// speedup vs baseline: 1.1386x; 1.1386x over previous
#include <cuda_runtime.h>
#include <cstdint>

// SpatialKNNEdge, round 15: exact two-pass threshold filter + hit compaction.
// grid(16, B), 512 threads, dynamic SMEM (~62KB, 2 blocks/SM).
//   Phase 0: stream zeros for the 128 owned rows (fire-and-forget, drains under compute).
//   Stage:   pos SoA into SMEM, padded to mult-of-16 with 1e15 sentinels.
//   Pass 1:  per (row, slice j%16) task: slice-min of d2. thr[row] = max of 16 slice mins
//            (>= true 16th smallest: 16 distinct candidates are <= it).
//   Pass 2:  rescan, compact hits (d2 <= thr) into per-row SMEM list (shared atomics).
//   Phase B: 4 lanes/row run exact lex-(d2,j) insertion over ~1/4 of the hit list each,
//            merge via shfl_xor bitonic (exact), scatter ones (block owns row).

#define NN      2048
#define FF      128
#define KK      16
#define BPB     16
#define THREADS 512
#define KROWS   64
#define NSL     16
#define CAP     256

struct Smem {
    float sx[NN], sy[NN], sz[NN];
    float thrpart[KROWS][NSL];
    float thr[KROWS];
    int   scnt[KROWS];
    unsigned short shits[KROWS][CAP];
};

__device__ __forceinline__ bool lexlt(float da, int ja, float db, int jb) {
    return (da < db) || (da == db && ja < jb);
}

__global__ __launch_bounds__(THREADS, 2)
void knn_adj_kernel(const float* __restrict__ nodes,
                    const int*   __restrict__ T,
                    const int*   __restrict__ taus,
                    float*       __restrict__ out)
{
    extern __shared__ unsigned char smem_raw[];
    Smem& sm = *reinterpret_cast<Smem*>(smem_raw);

    const int bx  = blockIdx.x;    // row residue class 0..15
    const int b   = blockIdx.y;    // batch
    const int tid = threadIdx.x;

    const int Tb = T[b];
    const int tb = taus[b];
    int maxJ = Tb + tb;
    if (maxJ > NN) maxJ = NN;
    const int maxJp = (maxJ + 15) & ~15;          // <= 2048

    const bool block_knn = (bx < tb);
    const float INF_F = 1e30f;

    // ---- Phase 0: stream zeros for the 128 owned rows (1 MB) ----
    {
        const float4 z = make_float4(0.0f, 0.0f, 0.0f, 0.0f);
        float4* obase = reinterpret_cast<float4*>(out + (size_t)b * NN * NN);
        #pragma unroll 4
        for (int idx = tid; idx < 128 * (NN / 4); idx += THREADS) {
            const int r = idx >> 9;
            const int c = idx & 511;
            __stcs(obase + (size_t)(bx + BPB * r) * (NN / 4) + c, z);
        }
    }

    if (tid < KROWS) sm.scnt[tid] = 0;

    // ---- Stage positions (SoA) with sentinel padding ----
    if (block_knn) {
        const float4* nrow = reinterpret_cast<const float4*>(nodes + (size_t)b * NN * FF);
        for (int j = tid; j < maxJp; j += THREADS) {
            if (j < maxJ) {
                float4 p = __ldg(nrow + (size_t)j * (FF / 4));
                sm.sx[j] = p.x; sm.sy[j] = p.y; sm.sz[j] = p.z;
            } else {
                sm.sx[j] = 1e15f; sm.sy[j] = 1e15f; sm.sz[j] = 1e15f;
            }
        }
    }
    __syncthreads();

    // Task mapping for passes 1&2: warp w, lane l -> row (w&1)*32 + l,
    // slices (w>>1) and (w>>1)+8. All lanes of a warp share the slice -> LDS broadcast.
    const int w  = tid >> 5;
    const int l  = tid & 31;
    const int rT = ((w & 1) << 5) + l;        // row slot 0..63
    const int iT = bx + BPB * rT;             // global row (<=1023); sink sg <= 2046 always in-bounds
    const int sgT = Tb + iT;

    if (block_knn) {
        const float spx = sm.sx[sgT], spy = sm.sy[sgT], spz = sm.sz[sgT];

        // ---- Pass 1: slice mins ----
        #pragma unroll
        for (int task = 0; task < 2; ++task) {
            const int s = (w >> 1) + (task << 3);
            float m0 = 3e30f, m1 = 3e30f, m2 = 3e30f, m3 = 3e30f;
            int j = s;
            for (; j + 48 < maxJp; j += 64) {
                { float dx=spx-sm.sx[j],    dy=spy-sm.sy[j],    dz=spz-sm.sz[j];    m0=fminf(m0,__fmaf_rn(dx,dx,__fmaf_rn(dy,dy,dz*dz))); }
                { float dx=spx-sm.sx[j+16], dy=spy-sm.sy[j+16], dz=spz-sm.sz[j+16]; m1=fminf(m1,__fmaf_rn(dx,dx,__fmaf_rn(dy,dy,dz*dz))); }
                { float dx=spx-sm.sx[j+32], dy=spy-sm.sy[j+32], dz=spz-sm.sz[j+32]; m2=fminf(m2,__fmaf_rn(dx,dx,__fmaf_rn(dy,dy,dz*dz))); }
                { float dx=spx-sm.sx[j+48], dy=spy-sm.sy[j+48], dz=spz-sm.sz[j+48]; m3=fminf(m3,__fmaf_rn(dx,dx,__fmaf_rn(dy,dy,dz*dz))); }
            }
            for (; j < maxJp; j += 16) {
                float dx=spx-sm.sx[j], dy=spy-sm.sy[j], dz=spz-sm.sz[j];
                m0 = fminf(m0, __fmaf_rn(dx,dx,__fmaf_rn(dy,dy,dz*dz)));
            }
            sm.thrpart[rT][s] = fminf(fminf(m0, m1), fminf(m2, m3));
        }
        __syncthreads();

        // ---- thr[r] = max of 16 slice mins ----
        if (tid < KROWS) {
            float t0 = 0.0f;
            #pragma unroll
            for (int s = 0; s < NSL; ++s) t0 = fmaxf(t0, sm.thrpart[tid][s]);
            sm.thr[tid] = t0;
        }
        __syncthreads();

        // ---- Pass 2: compact hits (d2 <= thr) into per-row lists ----
        if (iT < tb) {
            const float th = sm.thr[rT];
            #pragma unroll
            for (int task = 0; task < 2; ++task) {
                const int s = (w >> 1) + (task << 3);
                for (int j = s; j < maxJ; j += NSL) {
                    float dx = spx - sm.sx[j], dy = spy - sm.sy[j], dz = spz - sm.sz[j];
                    float d2 = __fmaf_rn(dx, dx, __fmaf_rn(dy, dy, dz * dz));
                    if (d2 <= th) {
                        int idx = atomicAdd(&sm.scnt[rT], 1);
                        if (idx < CAP) sm.shits[rT][idx] = (unsigned short)j;
                    }
                }
            }
        }
    }
    __syncthreads();

    // ---- Phase B: exact top-16 per row, 4 lanes/row ----
    if (block_knn && tid < 4 * KROWS) {
        const int r = tid >> 2;
        const int h = tid & 3;
        const int i = bx + BPB * r;

        float ad[KK];
        int   aj[KK];
        #pragma unroll
        for (int s = 0; s < KK; ++s) { ad[s] = INF_F; aj[s] = 0x7FFFFFFF; }

        if (i < tb) {
            const int sg = Tb + i;
            const float spx = sm.sx[sg], spy = sm.sy[sg], spz = sm.sz[sg];
            const int cnt = sm.scnt[r];

            if (cnt <= CAP) {
                for (int t = h; t < cnt; t += 4) {
                    const int j = sm.shits[r][t];
                    float dx = spx - sm.sx[j], dy = spy - sm.sy[j], dz = spz - sm.sz[j];
                    float cd = __fmaf_rn(dx, dx, __fmaf_rn(dy, dy, dz * dz));
                    int   cj = j;
                    #pragma unroll
                    for (int s = 0; s < KK; ++s) {
                        const bool lt = lexlt(cd, cj, ad[s], aj[s]);
                        const float td = lt ? ad[s] : cd;
                        const int   tj = lt ? aj[s] : cj;
                        ad[s] = lt ? cd : ad[s];
                        aj[s] = lt ? cj : aj[s];
                        cd = td; cj = tj;
                    }
                }
            } else {
                // Rare overflow fallback: guarded full scan (exact).
                for (int j = h; j < maxJ; j += 4) {
                    float dx = spx - sm.sx[j], dy = spy - sm.sy[j], dz = spz - sm.sz[j];
                    float cd = __fmaf_rn(dx, dx, __fmaf_rn(dy, dy, dz * dz));
                    int   cj = j;
                    if (lexlt(cd, cj, ad[KK - 1], aj[KK - 1])) {
                        #pragma unroll
                        for (int s = 0; s < KK; ++s) {
                            const bool lt = lexlt(cd, cj, ad[s], aj[s]);
                            const float td = lt ? ad[s] : cd;
                            const int   tj = lt ? aj[s] : cj;
                            ad[s] = lt ? cd : ad[s];
                            aj[s] = lt ? cj : aj[s];
                            cd = td; cj = tj;
                        }
                    }
                }
            }
        }

        // Merge the 4 sorted lists across lanes h^1, h^2 (exact lex bitonic).
        // Run for all lanes (INF lists for inactive rows) so shfl stays converged.
        #pragma unroll
        for (int m = 1; m <= 2; m <<= 1) {
            #pragma unroll
            for (int s = 0; s < KK / 2; ++s) {
                const int t = KK - 1 - s;
                const float pdT = __shfl_xor_sync(0xFFFFFFFFu, ad[t], m);
                const int   pjT = __shfl_xor_sync(0xFFFFFFFFu, aj[t], m);
                const float pdS = __shfl_xor_sync(0xFFFFFFFFu, ad[s], m);
                const int   pjS = __shfl_xor_sync(0xFFFFFFFFu, aj[s], m);
                const bool ls = lexlt(ad[s], aj[s], pdT, pjT);
                const float nds = ls ? ad[s] : pdT;
                const int   njs = ls ? aj[s] : pjT;
                const bool lt2 = lexlt(ad[t], aj[t], pdS, pjS);
                const float ndt = lt2 ? ad[t] : pdS;
                const int   njt = lt2 ? aj[t] : pjS;
                ad[s] = nds; aj[s] = njs;
                ad[t] = ndt; aj[t] = njt;
            }
            #pragma unroll
            for (int st = KK / 2; st >= 1; st >>= 1) {
                #pragma unroll
                for (int s = 0; s < KK; ++s) {
                    if ((s & st) == 0) {
                        const int v = s + st;
                        const bool sw = lexlt(ad[v], aj[v], ad[s], aj[s]);
                        const float td = sw ? ad[v] : ad[s];
                        const int   tj = sw ? aj[v] : aj[s];
                        const float ud = sw ? ad[s] : ad[v];
                        const int   uj = sw ? aj[s] : aj[v];
                        ad[s] = td; aj[s] = tj;
                        ad[v] = ud; aj[v] = uj;
                    }
                }
            }
        }

        // Scatter ones (zeros ordered by the earlier __syncthreads; block owns row).
        if (i < tb && h == 0) {
            const size_t base = ((size_t)(b * NN + i)) * NN;
            #pragma unroll
            for (int s = 0; s < KK; ++s) {
                if (ad[s] < INF_F && aj[s] < i) {
                    out[base + aj[s]] = 1.0f;
                }
            }
        }
    }
}

extern "C" void kernel_launch(void* const* d_in, const int* in_sizes, int n_in,
                              void* d_out, int out_size) {
    const float* nodes = (const float*)d_in[0];
    const int*   T     = (const int*)  d_in[1];
    const int*   taus  = (const int*)  d_in[2];
    float*       out   = (float*)      d_out;

    const int B = in_sizes[1];

    static bool attr_set = false;
    if (!attr_set) {
        cudaFuncSetAttribute(knn_adj_kernel,
                             cudaFuncAttributeMaxDynamicSharedMemorySize,
                             (int)sizeof(Smem));
        attr_set = true;
    }

    dim3 grid(BPB, B);
    knn_adj_kernel<<<grid, THREADS, sizeof(Smem)>>>(nodes, T, taus, out);
}